// round 2
// baseline (speedup 1.0000x reference)
#include <cuda_runtime.h>
#include <cuda_bf16.h>
#include <cstdint>

#define HDIM 128
#define MH 64
#define MAXB 2048
#define ROWS_PER_BLOCK 2048
#define ROWS_PER_LANE 1024
#define LN_EPS 1e-5f

// ---------------- scratch (static device globals; no allocation) ----------------
__device__ float    g_sum [MAXB * HDIM];
__device__ float    g_sq  [MAXB * HDIM];
__device__ unsigned g_minb[MAXB * HDIM];
__device__ unsigned g_maxb[MAXB * HDIM];
__device__ float    g_cnt [MAXB];

// order-preserving float <-> uint key (for atomicMin/atomicMax)
__device__ __forceinline__ unsigned fkey(float f) {
    unsigned b = __float_as_uint(f);
    return (b & 0x80000000u) ? ~b : (b | 0x80000000u);
}
__device__ __forceinline__ float funkey(unsigned k) {
    return __uint_as_float((k & 0x80000000u) ? (k ^ 0x80000000u) : ~k);
}

// ---------------- init: reset accumulators (runs every replay) ----------------
__global__ void init_kernel(int B) {
    int i = blockIdx.x * blockDim.x + threadIdx.x;
    int tot = B * HDIM;
    if (i < tot) {
        g_sum[i]  = 0.0f;
        g_sq[i]   = 0.0f;
        g_minb[i] = 0xFF800000u;  // fkey(+inf)  -> min identity
        g_maxb[i] = 0x007FFFFFu;  // fkey(-inf)  -> max identity
    }
    if (i < B) g_cnt[i] = 0.0f;
}

// ---------------- phase 1: segment reduction over sorted batch ----------------
__device__ __forceinline__ void flush_run(int seg, int col, float s, float q,
                                          float mn, float mx, int cnt) {
    int o = seg * HDIM + col;
    atomicAdd(&g_sum[o], s);
    atomicAdd(&g_sq[o], q);
    atomicMin(&g_minb[o], fkey(mn));
    atomicMax(&g_maxb[o], fkey(mx));
    if (col == 0) atomicAdd(&g_cnt[seg], (float)cnt);
}

__global__ void __launch_bounds__(256) seg_phase1(const float* __restrict__ x,
                                                  const int* __restrict__ batch,
                                                  int N) {
    __shared__ int sb[ROWS_PER_BLOCK];
    const int tid = threadIdx.x;
    const long long blockStart = (long long)blockIdx.x * ROWS_PER_BLOCK;
    int rows = (int)min((long long)ROWS_PER_BLOCK, (long long)N - blockStart);
    if (rows <= 0) return;

    for (int i = tid; i < rows; i += 256) sb[i] = batch[blockStart + i];
    __syncthreads();

    const int col  = tid & (HDIM - 1);
    const int lane = tid >> 7;               // 0 or 1
    const int lstart = lane * ROWS_PER_LANE;
    if (lstart >= rows) return;
    const int lend = min(lstart + ROWS_PER_LANE, rows);

    float s = 0.f, q = 0.f;
    float mn = __int_as_float(0x7F800000);   // +inf
    float mx = __int_as_float(0xFF800000);   // -inf
    int cur = -1, cnt = 0;

    const float* xp = x + (blockStart + lstart) * (long long)HDIM + col;

#define ACC(SG, V)                                                      \
    do {                                                                \
        if ((SG) != cur) {                                              \
            if (cnt) flush_run(cur, col, s, q, mn, mx, cnt);            \
            cur = (SG); s = (V); q = (V) * (V); mn = (V); mx = (V);     \
            cnt = 1;                                                    \
        } else {                                                        \
            s += (V); q += (V) * (V);                                   \
            mn = fminf(mn, (V)); mx = fmaxf(mx, (V)); cnt++;            \
        }                                                               \
    } while (0)

    int i = lstart;
    for (; i + 4 <= lend; i += 4) {
        float v0 = __ldg(xp);
        float v1 = __ldg(xp + HDIM);
        float v2 = __ldg(xp + 2 * HDIM);
        float v3 = __ldg(xp + 3 * HDIM);
        int s0 = sb[i], s1 = sb[i + 1], s2 = sb[i + 2], s3 = sb[i + 3];
        ACC(s0, v0); ACC(s1, v1); ACC(s2, v2); ACC(s3, v3);
        xp += 4 * HDIM;
    }
    for (; i < lend; ++i) {
        float v = __ldg(xp);
        int sg = sb[i];
        ACC(sg, v);
        xp += HDIM;
    }
#undef ACC
    if (cnt) flush_run(cur, col, s, q, mn, mx, cnt);
}

// ---------------- phase 2: concat + MLP + LN + residual ----------------
__global__ void __launch_bounds__(128) mlp_kernel(
    const float* __restrict__ u,
    const float* __restrict__ W0, const float* __restrict__ b0,
    const float* __restrict__ W1, const float* __restrict__ b1,
    const float* __restrict__ W2, const float* __restrict__ b2,
    const float* __restrict__ lng, const float* __restrict__ lnb,
    const float* __restrict__ W3, const float* __restrict__ b3,
    float* __restrict__ out) {
    const int b = blockIdx.x;
    const int t = threadIdx.x;

    __shared__ float concat[5 * HDIM];
    __shared__ float h[MH];
    __shared__ float hn[MH];
    __shared__ float hp[128];
    __shared__ float mu_s, rstd_s;

    // build concat = [u, s, min, max, var]
    {
        float cntv = fmaxf(g_cnt[b], 1.0f);
        int o = b * HDIM + t;
        float sv = g_sum[o];
        float me = sv / cntv;
        concat[t]            = u[o];
        concat[HDIM + t]     = sv;
        concat[2 * HDIM + t] = funkey(g_minb[o]);
        concat[3 * HDIM + t] = funkey(g_maxb[o]);
        concat[4 * HDIM + t] = g_sq[o] / cntv - me * me;
    }
    __syncthreads();

    const int m = t & 63;
    const int half = t >> 6;

    // layer 0: 640 -> 64 (split K over two halves)
    {
        float acc = 0.f;
        const float* w = W0 + (size_t)half * 320 * MH + m;
        const float* c = concat + half * 320;
#pragma unroll 8
        for (int k = 0; k < 320; ++k) acc += c[k] * __ldg(&w[k * MH]);
        hp[t] = acc;
    }
    __syncthreads();
    if (t < MH) h[t] = fmaxf(hp[t] + hp[t + 64] + b0[t], 0.f);
    __syncthreads();

    // layer 1: 64 -> 64
    {
        float acc = 0.f;
        const float* w = W1 + (size_t)half * 32 * MH + m;
        const float* c = h + half * 32;
#pragma unroll
        for (int k = 0; k < 32; ++k) acc += c[k] * __ldg(&w[k * MH]);
        hp[t] = acc;
    }
    __syncthreads();
    if (t < MH) hn[t] = fmaxf(hp[t] + hp[t + 64] + b1[t], 0.f);
    __syncthreads();

    // layer 2: 64 -> 64
    {
        float acc = 0.f;
        const float* w = W2 + (size_t)half * 32 * MH + m;
        const float* c = hn + half * 32;
#pragma unroll
        for (int k = 0; k < 32; ++k) acc += c[k] * __ldg(&w[k * MH]);
        hp[t] = acc;
    }
    __syncthreads();
    if (t < MH) h[t] = fmaxf(hp[t] + hp[t + 64] + b2[t], 0.f);
    __syncthreads();

    // layernorm over the 64 features
    if (t == 0) {
        float mu = 0.f;
        for (int k = 0; k < MH; ++k) mu += h[k];
        mu /= (float)MH;
        float v = 0.f;
        for (int k = 0; k < MH; ++k) { float d = h[k] - mu; v += d * d; }
        mu_s = mu;
        rstd_s = rsqrtf(v / (float)MH + LN_EPS);
    }
    __syncthreads();
    if (t < MH) hn[t] = (h[t] - mu_s) * rstd_s * lng[t] + lnb[t];
    __syncthreads();

    // output layer: 64 -> 128 + residual
    float acc = b3[t];
#pragma unroll 8
    for (int k = 0; k < MH; ++k) acc += hn[k] * __ldg(&W3[k * HDIM + t]);
    out[b * HDIM + t] = u[b * HDIM + t] + acc;
}

// ---------------- launch ----------------
extern "C" void kernel_launch(void* const* d_in, const int* in_sizes, int n_in,
                              void* d_out, int out_size) {
    const float* x     = (const float*)d_in[0];
    // d_in[1] edge_index, d_in[2] edge_attr : unused by the forward
    const float* u     = (const float*)d_in[3];
    const int*   batch = (const int*)d_in[4];
    const float* W0    = (const float*)d_in[5];
    const float* b0    = (const float*)d_in[6];
    const float* W1    = (const float*)d_in[7];
    const float* b1    = (const float*)d_in[8];
    const float* W2    = (const float*)d_in[9];
    const float* b2    = (const float*)d_in[10];
    const float* lng   = (const float*)d_in[11];
    const float* lnb   = (const float*)d_in[12];
    const float* W3    = (const float*)d_in[13];
    const float* b3    = (const float*)d_in[14];
    float* out = (float*)d_out;

    const int N = in_sizes[0] / HDIM;
    int B = in_sizes[3] / HDIM;
    if (B > MAXB) B = MAXB;

    const int initTot = B * HDIM;
    init_kernel<<<(initTot + 255) / 256, 256>>>(B);

    const int nBlocks = (N + ROWS_PER_BLOCK - 1) / ROWS_PER_BLOCK;
    seg_phase1<<<nBlocks, 256>>>(x, batch, N);

    mlp_kernel<<<B, 128>>>(u, W0, b0, W1, b1, W2, b2, lng, lnb, W3, b3, out);
}

// round 3
// speedup vs baseline: 1.2030x; 1.2030x over previous
#include <cuda_runtime.h>
#include <cuda_bf16.h>
#include <cstdint>

#define HDIM 128
#define MH 64
#define MAXB 2048
#define ROWS_PER_BLOCK 1024
#define ROWS_PER_WARP 128
#define LN_EPS 1e-5f

// ---------------- scratch (static device globals; no allocation) ----------------
__device__ float    g_sum [MAXB * HDIM];
__device__ float    g_sq  [MAXB * HDIM];
__device__ unsigned g_minb[MAXB * HDIM];
__device__ unsigned g_maxb[MAXB * HDIM];
__device__ float    g_cnt [MAXB];

// order-preserving float <-> uint key (for atomicMin/atomicMax)
__device__ __forceinline__ unsigned fkey(float f) {
    unsigned b = __float_as_uint(f);
    return (b & 0x80000000u) ? ~b : (b | 0x80000000u);
}
__device__ __forceinline__ float funkey(unsigned k) {
    return __uint_as_float((k & 0x80000000u) ? (k ^ 0x80000000u) : ~k);
}

// ---------------- init: reset accumulators (runs every replay) ----------------
__global__ void init_kernel(int B) {
    int i = blockIdx.x * blockDim.x + threadIdx.x;
    int tot = B * HDIM;
    if (i < tot) {
        g_sum[i]  = 0.0f;
        g_sq[i]   = 0.0f;
        g_minb[i] = 0xFF800000u;  // fkey(+inf)  -> min identity
        g_maxb[i] = 0x007FFFFFu;  // fkey(-inf)  -> max identity
    }
    if (i < B) g_cnt[i] = 0.0f;
}

// ---------------- phase 1: segment reduction, warp-per-row float4 ----------------
struct Acc4 {
    float4 s, q, mn, mx;
    int cnt;
};

__device__ __forceinline__ void acc_reset(Acc4& a, const float4& v) {
    a.s = v;
    a.q = make_float4(v.x * v.x, v.y * v.y, v.z * v.z, v.w * v.w);
    a.mn = v;
    a.mx = v;
    a.cnt = 1;
}
__device__ __forceinline__ void acc_add(Acc4& a, const float4& v) {
    a.s.x += v.x; a.s.y += v.y; a.s.z += v.z; a.s.w += v.w;
    a.q.x = fmaf(v.x, v.x, a.q.x);
    a.q.y = fmaf(v.y, v.y, a.q.y);
    a.q.z = fmaf(v.z, v.z, a.q.z);
    a.q.w = fmaf(v.w, v.w, a.q.w);
    a.mn.x = fminf(a.mn.x, v.x); a.mn.y = fminf(a.mn.y, v.y);
    a.mn.z = fminf(a.mn.z, v.z); a.mn.w = fminf(a.mn.w, v.w);
    a.mx.x = fmaxf(a.mx.x, v.x); a.mx.y = fmaxf(a.mx.y, v.y);
    a.mx.z = fmaxf(a.mx.z, v.z); a.mx.w = fmaxf(a.mx.w, v.w);
}

__device__ __forceinline__ void acc_flush(const Acc4& a, int seg, int colbase, int lane) {
    int o = seg * HDIM + colbase;
    atomicAdd(&g_sum[o + 0], a.s.x);
    atomicAdd(&g_sum[o + 1], a.s.y);
    atomicAdd(&g_sum[o + 2], a.s.z);
    atomicAdd(&g_sum[o + 3], a.s.w);
    atomicAdd(&g_sq[o + 0], a.q.x);
    atomicAdd(&g_sq[o + 1], a.q.y);
    atomicAdd(&g_sq[o + 2], a.q.z);
    atomicAdd(&g_sq[o + 3], a.q.w);
    atomicMin(&g_minb[o + 0], fkey(a.mn.x));
    atomicMin(&g_minb[o + 1], fkey(a.mn.y));
    atomicMin(&g_minb[o + 2], fkey(a.mn.z));
    atomicMin(&g_minb[o + 3], fkey(a.mn.w));
    atomicMax(&g_maxb[o + 0], fkey(a.mx.x));
    atomicMax(&g_maxb[o + 1], fkey(a.mx.y));
    atomicMax(&g_maxb[o + 2], fkey(a.mx.z));
    atomicMax(&g_maxb[o + 3], fkey(a.mx.w));
    if (lane == 0) atomicAdd(&g_cnt[seg], (float)a.cnt);
}

__global__ void __launch_bounds__(256) seg_phase1(const float4* __restrict__ x4,
                                                  const int* __restrict__ batch,
                                                  int N) {
    __shared__ int sb[ROWS_PER_BLOCK];
    const int tid = threadIdx.x;
    const int warp = tid >> 5;
    const int lane = tid & 31;
    const long long blockStart = (long long)blockIdx.x * ROWS_PER_BLOCK;
    const int rows = (int)min((long long)ROWS_PER_BLOCK, (long long)N - blockStart);
    if (rows <= 0) return;

    for (int i = tid; i < rows; i += 256) sb[i] = batch[blockStart + i];
    __syncthreads();

    const int wstart = warp * ROWS_PER_WARP;
    if (wstart >= rows) return;
    const int wend = min(wstart + ROWS_PER_WARP, rows);

    // each warp owns full rows; lane covers columns [lane*4, lane*4+4)
    const float4* xp = x4 + (blockStart + wstart) * (HDIM / 4) + lane;

    Acc4 a;
    int cur = sb[wstart];
    {
        float4 v0 = __ldcs(xp);
        acc_reset(a, v0);
        xp += HDIM / 4;
    }

    int i = wstart + 1;
    // groups of 8 rows
    for (; i + 8 <= wend; i += 8) {
        float4 v[8];
#pragma unroll
        for (int j = 0; j < 8; ++j) v[j] = __ldcs(xp + j * (HDIM / 4));
        if (sb[i + 7] == cur) {
            // sorted => all 8 in current segment: branch-free accumulate
#pragma unroll
            for (int j = 0; j < 8; ++j) acc_add(a, v[j]);
            a.cnt += 8;
        } else {
#pragma unroll
            for (int j = 0; j < 8; ++j) {
                int sg = sb[i + j];
                if (sg != cur) {
                    acc_flush(a, cur, lane * 4, lane);
                    cur = sg;
                    acc_reset(a, v[j]);
                } else {
                    acc_add(a, v[j]);
                    a.cnt++;
                }
            }
        }
        xp += 8 * (HDIM / 4);
    }
    for (; i < wend; ++i) {
        float4 v = __ldcs(xp);
        int sg = sb[i];
        if (sg != cur) {
            acc_flush(a, cur, lane * 4, lane);
            cur = sg;
            acc_reset(a, v);
        } else {
            acc_add(a, v);
            a.cnt++;
        }
        xp += HDIM / 4;
    }
    acc_flush(a, cur, lane * 4, lane);
}

// ---------------- phase 2: concat + MLP + LN + residual ----------------
__global__ void __launch_bounds__(128) mlp_kernel(
    const float* __restrict__ u,
    const float* __restrict__ W0, const float* __restrict__ b0,
    const float* __restrict__ W1, const float* __restrict__ b1,
    const float* __restrict__ W2, const float* __restrict__ b2,
    const float* __restrict__ lng, const float* __restrict__ lnb,
    const float* __restrict__ W3, const float* __restrict__ b3,
    float* __restrict__ out) {
    const int b = blockIdx.x;
    const int t = threadIdx.x;

    __shared__ float concat[5 * HDIM];
    __shared__ float h[MH];
    __shared__ float hn[MH];
    __shared__ float hp[128];
    __shared__ float mu_s, rstd_s;

    // build concat = [u, s, min, max, var]
    {
        float cntv = fmaxf(g_cnt[b], 1.0f);
        int o = b * HDIM + t;
        float sv = g_sum[o];
        float me = sv / cntv;
        concat[t]            = u[o];
        concat[HDIM + t]     = sv;
        concat[2 * HDIM + t] = funkey(g_minb[o]);
        concat[3 * HDIM + t] = funkey(g_maxb[o]);
        concat[4 * HDIM + t] = g_sq[o] / cntv - me * me;
    }
    __syncthreads();

    const int m = t & 63;
    const int half = t >> 6;

    // layer 0: 640 -> 64 (split K over two halves)
    {
        float acc = 0.f;
        const float* w = W0 + (size_t)half * 320 * MH + m;
        const float* c = concat + half * 320;
#pragma unroll 8
        for (int k = 0; k < 320; ++k) acc += c[k] * __ldg(&w[k * MH]);
        hp[t] = acc;
    }
    __syncthreads();
    if (t < MH) h[t] = fmaxf(hp[t] + hp[t + 64] + b0[t], 0.f);
    __syncthreads();

    // layer 1: 64 -> 64
    {
        float acc = 0.f;
        const float* w = W1 + (size_t)half * 32 * MH + m;
        const float* c = h + half * 32;
#pragma unroll
        for (int k = 0; k < 32; ++k) acc += c[k] * __ldg(&w[k * MH]);
        hp[t] = acc;
    }
    __syncthreads();
    if (t < MH) hn[t] = fmaxf(hp[t] + hp[t + 64] + b1[t], 0.f);
    __syncthreads();

    // layer 2: 64 -> 64
    {
        float acc = 0.f;
        const float* w = W2 + (size_t)half * 32 * MH + m;
        const float* c = hn + half * 32;
#pragma unroll
        for (int k = 0; k < 32; ++k) acc += c[k] * __ldg(&w[k * MH]);
        hp[t] = acc;
    }
    __syncthreads();
    if (t < MH) h[t] = fmaxf(hp[t] + hp[t + 64] + b2[t], 0.f);
    __syncthreads();

    // layernorm over the 64 features
    if (t == 0) {
        float mu = 0.f;
        for (int k = 0; k < MH; ++k) mu += h[k];
        mu /= (float)MH;
        float v = 0.f;
        for (int k = 0; k < MH; ++k) { float d = h[k] - mu; v += d * d; }
        mu_s = mu;
        rstd_s = rsqrtf(v / (float)MH + LN_EPS);
    }
    __syncthreads();
    if (t < MH) hn[t] = (h[t] - mu_s) * rstd_s * lng[t] + lnb[t];
    __syncthreads();

    // output layer: 64 -> 128 + residual
    float acc = b3[t];
#pragma unroll 8
    for (int k = 0; k < MH; ++k) acc += hn[k] * __ldg(&W3[k * HDIM + t]);
    out[b * HDIM + t] = u[b * HDIM + t] + acc;
}

// ---------------- launch ----------------
extern "C" void kernel_launch(void* const* d_in, const int* in_sizes, int n_in,
                              void* d_out, int out_size) {
    const float* x     = (const float*)d_in[0];
    // d_in[1] edge_index, d_in[2] edge_attr : unused by the forward
    const float* u     = (const float*)d_in[3];
    const int*   batch = (const int*)d_in[4];
    const float* W0    = (const float*)d_in[5];
    const float* b0    = (const float*)d_in[6];
    const float* W1    = (const float*)d_in[7];
    const float* b1    = (const float*)d_in[8];
    const float* W2    = (const float*)d_in[9];
    const float* b2    = (const float*)d_in[10];
    const float* lng   = (const float*)d_in[11];
    const float* lnb   = (const float*)d_in[12];
    const float* W3    = (const float*)d_in[13];
    const float* b3    = (const float*)d_in[14];
    float* out = (float*)d_out;

    const int N = in_sizes[0] / HDIM;
    int B = in_sizes[3] / HDIM;
    if (B > MAXB) B = MAXB;

    const int initTot = B * HDIM;
    init_kernel<<<(initTot + 255) / 256, 256>>>(B);

    const int nBlocks = (N + ROWS_PER_BLOCK - 1) / ROWS_PER_BLOCK;
    seg_phase1<<<nBlocks, 256>>>((const float4*)x, batch, N);

    mlp_kernel<<<B, 128>>>(u, W0, b0, W1, b1, W2, b2, lng, lnb, W3, b3, out);
}